// round 16
// baseline (speedup 1.0000x reference)
#include <cuda_runtime.h>
#include <math.h>

#define N_NODES 128000
#define F_IN    128
#define D_LAT   32
#define B_G     256
#define NPG     500
#define K_TOP   30
#define L_LAYERS 3
#define E_EDGES 2048000

#define N_CHUNKS 4
#define CHUNK    (N_NODES / N_CHUNKS)    // 32000 nodes per chunk

// packed f32x2 add (Blackwell): only reachable via PTX. Used ONLY where both
// operands are naturally 64-bit register pairs (LDG.64 results).
__device__ __forceinline__ void add2(float2& a, float2 b) {
    unsigned long long au = *reinterpret_cast<unsigned long long*>(&a);
    unsigned long long bu = *reinterpret_cast<unsigned long long*>(&b);
    asm("add.rn.f32x2 %0, %1, %2;" : "=l"(au) : "l"(au), "l"(bu));
    a = *reinterpret_cast<float2*>(&au);
}

// ---------------- device scratch (static, no allocation) ----------------
__device__ float g_e0[N_NODES * D_LAT];
__device__ float g_e1[N_NODES * D_LAT];
__device__ float g_e2[N_NODES * D_LAT];
__device__ float g_e3[N_NODES * D_LAT];
__device__ float g_neig[N_NODES * D_LAT];
__device__ int   g_counts[N_NODES];
__device__ int   g_rowptr[N_NODES + 1];
__device__ int   g_cursor[N_NODES];
__device__ int   g_bsums[128];
__device__ int   g_col[E_EDGES];

// ---------------- edge histogram (stream B) ----------------
__global__ void k_hist(const int4* __restrict__ edst4) {
    if (blockIdx.x == 0 && threadIdx.x < 128) g_bsums[threadIdx.x] = 0;  // scan flags
    int i = blockIdx.x * blockDim.x + threadIdx.x;
    int4 v = edst4[i];
    atomicAdd(&g_counts[v.x], 1);
    atomicAdd(&g_counts[v.y], 1);
    atomicAdd(&g_counts[v.z], 1);
    atomicAdd(&g_counts[v.w], 1);
}

// ---------------- mlp0: ego0 = relu(X@w0a+b0a)@w0b+b0b ---------------------
// Warp per 16 rows: 1 weight-LDS feeds 16 FMAs; 16-deep row ILP hides LDS lat.
#define MLP0_GRID 1000
#define MLP0_SMEM (F_IN * D_LAT * 4 + 8 * 16 * F_IN * 4)   // 16KB + 64KB
__global__ void __launch_bounds__(256, 2) k_mlp0(
        const float* __restrict__ X,
        const float* __restrict__ w0a, const float* __restrict__ b0a,
        const float* __restrict__ w0b, const float* __restrict__ b0b) {
    extern __shared__ float smem0[];
    float* ws = smem0;                          // w0a [k][lane], 16KB
    float* sx = smem0 + F_IN * D_LAT;           // 16 rows x 128 floats per warp
    int tid  = threadIdx.x;
    int lane = tid & 31;
    int w    = tid >> 5;

    for (int i = tid; i < F_IN * D_LAT; i += 256) ws[i] = w0a[i];
    float wb[32];
    #pragma unroll
    for (int j = 0; j < 32; j++) wb[j] = w0b[j * 32 + lane];
    float b0 = b0a[lane], b1 = b0b[lane];
    __syncthreads();

    int warp  = blockIdx.x * 8 + w;
    int rbase = warp * 16;
    float* xw = &sx[w * 2048];

    #pragma unroll
    for (int rr = 0; rr < 16; rr++) {
        float4 v = *(const float4*)&X[(rbase + rr) * F_IN + lane * 4];
        *(float4*)&xw[rr * 128 + lane * 4] = v;
    }
    __syncwarp();

    float acc[16];
    #pragma unroll
    for (int rr = 0; rr < 16; rr++) acc[rr] = b0;
    #pragma unroll 2
    for (int k = 0; k < F_IN; k += 4) {
        float w0 = ws[(k + 0) * 32 + lane];
        float w1 = ws[(k + 1) * 32 + lane];
        float w2 = ws[(k + 2) * 32 + lane];
        float w3 = ws[(k + 3) * 32 + lane];
        #pragma unroll
        for (int rr = 0; rr < 16; rr++) {
            float4 x4 = *(const float4*)&xw[rr * 128 + k];
            float p0 = fmaf(x4.x, w0, acc[rr]);
            float p1 = fmaf(x4.y, w1, p0);
            float p2 = fmaf(x4.z, w2, p1);
            acc[rr]  = fmaf(x4.w, w3, p2);
        }
    }
    float h[16];
    #pragma unroll
    for (int rr = 0; rr < 16; rr++) h[rr] = fmaxf(acc[rr], 0.f);

    __syncwarp();
    #pragma unroll
    for (int rr = 0; rr < 16; rr++) xw[rr * 32 + lane] = h[rr];
    __syncwarp();

    float o[16];
    #pragma unroll
    for (int rr = 0; rr < 16; rr++) o[rr] = b1;
    #pragma unroll
    for (int j = 0; j < 32; j += 4) {
        #pragma unroll
        for (int rr = 0; rr < 16; rr++) {
            float4 h4 = *(const float4*)&xw[rr * 32 + j];
            float p0 = fmaf(h4.x, wb[j + 0], o[rr]);
            float p1 = fmaf(h4.y, wb[j + 1], p0);
            float p2 = fmaf(h4.z, wb[j + 2], p1);
            o[rr]    = fmaf(h4.w, wb[j + 3], p2);
        }
    }
    #pragma unroll
    for (int rr = 0; rr < 16; rr++)
        g_e0[(rbase + rr) * 32 + lane] = o[rr];
}

// ------------- single-pass scan: counts -> rowptr/cursor (lookback) --------
#define SCAN_FLAG 0x40000000
__global__ void __launch_bounds__(1024) k_scan() {
    __shared__ int swarp[32];
    __shared__ int sbase;
    int tid  = threadIdx.x;
    int lane = tid & 31;
    int wid  = tid >> 5;
    int b    = blockIdx.x;
    int gid  = b * 1024 + tid;

    int v = g_counts[gid];
    int x = v;
    #pragma unroll
    for (int off = 1; off < 32; off <<= 1) {
        int t = __shfl_up_sync(0xFFFFFFFFu, x, off);
        if (lane >= off) x += t;
    }
    if (lane == 31) swarp[wid] = x;
    __syncthreads();
    if (wid == 0) {
        int y = swarp[lane];
        #pragma unroll
        for (int off = 1; off < 32; off <<= 1) {
            int t = __shfl_up_sync(0xFFFFFFFFu, y, off);
            if (lane >= off) y += t;
        }
        swarp[lane] = y;
    }
    __syncthreads();
    int wbase = (wid > 0) ? swarp[wid - 1] : 0;
    int local_excl = wbase + x - v;
    int blocksum   = swarp[31];

    if (tid == 0) {
        __threadfence();
        atomicExch(&g_bsums[b], blocksum | SCAN_FLAG);
    }
    if (wid == 0) {
        int pre = 0;
        for (int i = lane; i < b; i += 32) {
            int t;
            do { t = atomicAdd(&g_bsums[i], 0); } while (!(t & SCAN_FLAG));
            pre += t & (SCAN_FLAG - 1);
        }
        #pragma unroll
        for (int off = 16; off >= 1; off >>= 1)
            pre += __shfl_down_sync(0xFFFFFFFFu, pre, off);
        if (lane == 0) sbase = pre;
    }
    __syncthreads();
    int rp = sbase + local_excl;
    g_rowptr[gid] = rp;
    g_cursor[gid] = rp;
    if (gid == N_NODES - 1) g_rowptr[N_NODES] = E_EDGES;
}

__global__ void k_scatter(const int4* __restrict__ esrc4, const int4* __restrict__ edst4) {
    int i = blockIdx.x * blockDim.x + threadIdx.x;
    int4 s = esrc4[i];
    int4 d = edst4[i];
    int p;
    p = atomicAdd(&g_cursor[d.x], 1); g_col[p] = s.x;
    p = atomicAdd(&g_cursor[d.y], 1); g_col[p] = s.y;
    p = atomicAdd(&g_cursor[d.z], 1); g_col[p] = s.z;
    p = atomicAdd(&g_cursor[d.w], 1); g_col[p] = s.w;
}

// ---------------- SpMM over node range [lo, lo+CHUNK) ----------------------
// Each 16-lane half-warp owns ONE node. Lane = float2 (2 channels). (R12 form)
__global__ void __launch_bounds__(256) k_spmm(const float* __restrict__ ego_in,
                                              int lo) {
    int gwarp = (blockIdx.x * blockDim.x + threadIdx.x) >> 5;
    int lane  = threadIdx.x & 31;
    int half  = lane >> 4;
    int li    = lane & 15;
    int node  = lo + gwarp * 2 + half;
    int e   = g_rowptr[node];
    int end = g_rowptr[node + 1];
    const float2* __restrict__ eg2 = (const float2*)ego_in;

    float2 a0 = make_float2(0.f, 0.f);
    float2 a1 = make_float2(0.f, 0.f);
    float2 a2 = make_float2(0.f, 0.f);
    float2 a3 = make_float2(0.f, 0.f);

    for (; e + 3 < end; e += 4) {
        int s0 = g_col[e + 0];
        int s1 = g_col[e + 1];
        int s2 = g_col[e + 2];
        int s3 = g_col[e + 3];
        float2 v0 = eg2[s0 * 16 + li];
        float2 v1 = eg2[s1 * 16 + li];
        float2 v2 = eg2[s2 * 16 + li];
        float2 v3 = eg2[s3 * 16 + li];
        add2(a0, v0);
        add2(a1, v1);
        add2(a2, v2);
        add2(a3, v3);
    }
    for (; e < end; e++) {
        int s = g_col[e];
        add2(a0, eg2[s * 16 + li]);
    }
    add2(a0, a1);
    add2(a2, a3);
    add2(a0, a2);

    ((float2*)g_neig)[node * 16 + li] = a0;
}

// ---------------- layer MLP over row range [lo, hi) -------------------------
#define MLP1_GRID 148
__global__ void __launch_bounds__(256, 2) k_mlp1(
        const float* __restrict__ W1a, const float* __restrict__ B1a,
        const float* __restrict__ W1b, const float* __restrict__ B1b,
        const float* __restrict__ ego_in, float* __restrict__ ego_out,
        int l, int lo, int hi) {
    __shared__ float sm[8 * 96];
    int tid  = threadIdx.x;
    int lane = tid & 31;
    float* sw = &sm[(tid >> 5) * 96];

    const float* Wa = W1a + l * 96 * 32;
    const float* Wb = W1b + l * 32 * 32;
    float wea[32], wna[32], wb[32];
    #pragma unroll
    for (int j = 0; j < 32; j++) {
        float wc = Wa[(64 + j) * 32 + lane];
        wea[j] = Wa[j * 32 + lane] + wc;
        wna[j] = Wa[(32 + j) * 32 + lane] + wc;
        wb[j]  = Wb[j * 32 + lane];
    }
    float ba = B1a[l * 32 + lane], bb = B1b[l * 32 + lane];

    int warp   = (blockIdx.x * 256 + tid) >> 5;
    int nwarps = (MLP1_GRID * 256) >> 5;

    int row = lo + warp;
    float ev = 0.f, nv = 0.f;
    if (row < hi) {
        ev = ego_in[row * 32 + lane];
        nv = g_neig[row * 32 + lane];
    }
    for (; row < hi; row += nwarps) {
        int nrow = row + nwarps;
        float evn = 0.f, nvn = 0.f;
        if (nrow < hi) {
            evn = ego_in[nrow * 32 + lane];
            nvn = g_neig[nrow * 32 + lane];
        }

        sw[lane]      = ev;
        sw[32 + lane] = nv;
        __syncwarp();

        float e0 = ba, e1 = 0.f, e2 = 0.f, e3 = 0.f;
        float n0 = 0.f, n1 = 0.f, n2 = 0.f, n3 = 0.f;
        #pragma unroll
        for (int j = 0; j < 32; j += 4) {
            float4 e4 = *(const float4*)&sw[j];
            float4 n4 = *(const float4*)&sw[32 + j];
            e0 = fmaf(e4.x, wea[j + 0], e0);
            e1 = fmaf(e4.y, wea[j + 1], e1);
            e2 = fmaf(e4.z, wea[j + 2], e2);
            e3 = fmaf(e4.w, wea[j + 3], e3);
            n0 = fmaf(n4.x, wna[j + 0], n0);
            n1 = fmaf(n4.y, wna[j + 1], n1);
            n2 = fmaf(n4.z, wna[j + 2], n2);
            n3 = fmaf(n4.w, wna[j + 3], n3);
        }
        float h = fmaxf(((e0 + e1) + (e2 + e3)) + ((n0 + n1) + (n2 + n3)), 0.f);
        sw[64 + lane] = h;
        __syncwarp();

        float o0 = bb, o1 = 0.f, o2 = 0.f, o3 = 0.f;
        #pragma unroll
        for (int j = 0; j < 32; j += 4) {
            float4 h4 = *(const float4*)&sw[64 + j];
            o0 = fmaf(h4.x, wb[j + 0], o0);
            o1 = fmaf(h4.y, wb[j + 1], o1);
            o2 = fmaf(h4.z, wb[j + 2], o2);
            o3 = fmaf(h4.w, wb[j + 3], o3);
        }
        ego_out[row * 32 + lane] = (o0 + o1) + (o2 + o3);
        __syncwarp();
        ev = evn; nv = nvn;
    }
}

// ---------------- per-graph top-K + alpha combine + relu -------------------
__global__ void k_topk(const float* __restrict__ alpha, float* __restrict__ dout) {
    __shared__ float sv[512];
    __shared__ int   si[512];
    __shared__ float rv[512];
    __shared__ int   ri[512];
    __shared__ int   sel[K_TOP];
    int g = blockIdx.x, tid = threadIdx.x;

    for (int i = tid; i < 512; i += 256) {
        if (i < NPG) { sv[i] = g_e3[(g * NPG + i) * 32 + 31]; si[i] = i; }
        else         { sv[i] = -3.402823466e38f;              si[i] = i; }
    }
    __syncthreads();

    for (int r = 0; r < K_TOP; r++) {
        for (int i = tid; i < 512; i += 256) { rv[i] = sv[i]; ri[i] = si[i]; }
        __syncthreads();
        for (int s = 256; s >= 1; s >>= 1) {
            if (tid < s) {
                float v1 = rv[tid], v2 = rv[tid + s];
                int   i1 = ri[tid], i2 = ri[tid + s];
                if (v2 > v1 || (v2 == v1 && i2 < i1)) { rv[tid] = v2; ri[tid] = i2; }
            }
            __syncthreads();
        }
        if (tid == 0) {
            int best = ri[0];
            sel[r] = best;
            sv[best] = -3.402823466e38f;
        }
        __syncthreads();
    }

    float a0v = alpha[0], a1v = alpha[1], a2v = alpha[2], a3v = alpha[3];
    for (int i = tid; i < K_TOP * 32; i += 256) {
        int r = i >> 5, c = i & 31;
        int idx = (g * NPG + sel[r]) * 32 + c;
        float v = a0v * g_e0[idx];
        v = fmaf(a1v, g_e1[idx], v);
        v = fmaf(a2v, g_e2[idx], v);
        v = fmaf(a3v, g_e3[idx], v);
        dout[g * (K_TOP * 32) + i] = fmaxf(v, 0.f);
    }
}

// ---------------- launch -----------------------------------------------
extern "C" void kernel_launch(void* const* d_in, const int* in_sizes, int n_in,
                              void* d_out, int out_size) {
    const float* node_feat = (const float*)d_in[0];
    const float* alpha     = (const float*)d_in[1];
    const float* w0a       = (const float*)d_in[2];
    const float* b0a       = (const float*)d_in[3];
    const float* w0b       = (const float*)d_in[4];
    const float* b0b       = (const float*)d_in[5];
    const float* W1a       = (const float*)d_in[6];
    const float* B1a       = (const float*)d_in[7];
    const float* W1b       = (const float*)d_in[8];
    const float* B1b       = (const float*)d_in[9];
    const int*   esrc      = (const int*)d_in[10];
    const int*   edst      = (const int*)d_in[11];
    float*       dout      = (float*)d_out;

    static cudaStream_t sB = nullptr;
    static cudaEvent_t  evFork = nullptr, evA = nullptr, evB = nullptr;
    static cudaEvent_t  evS[N_CHUNKS] = {};
    if (sB == nullptr) {
        cudaStreamCreateWithFlags(&sB, cudaStreamNonBlocking);
        cudaEventCreateWithFlags(&evFork, cudaEventDisableTiming);
        cudaEventCreateWithFlags(&evA, cudaEventDisableTiming);
        cudaEventCreateWithFlags(&evB, cudaEventDisableTiming);
        for (int i = 0; i < N_CHUNKS; i++)
            cudaEventCreateWithFlags(&evS[i], cudaEventDisableTiming);
        cudaFuncSetAttribute(k_mlp0, cudaFuncAttributeMaxDynamicSharedMemorySize,
                             MLP0_SMEM);
    }

    void* counts_ptr = nullptr;
    cudaGetSymbolAddress(&counts_ptr, g_counts);

    float* e[4];
    {
        void* p;
        cudaGetSymbolAddress(&p, g_e0); e[0] = (float*)p;
        cudaGetSymbolAddress(&p, g_e1); e[1] = (float*)p;
        cudaGetSymbolAddress(&p, g_e2); e[2] = (float*)p;
        cudaGetSymbolAddress(&p, g_e3); e[3] = (float*)p;
    }

    // fork: stream B builds the CSR while stream 0 runs mlp0
    cudaEventRecord(evFork, 0);
    cudaStreamWaitEvent(sB, evFork, 0);

    cudaMemsetAsync(counts_ptr, 0, N_NODES * sizeof(int), sB);
    k_hist<<<E_EDGES / 4 / 256, 256, 0, sB>>>((const int4*)edst);
    k_scan<<<125, 1024, 0, sB>>>();
    k_scatter<<<E_EDGES / 4 / 256, 256, 0, sB>>>((const int4*)esrc, (const int4*)edst);

    k_mlp0<<<MLP0_GRID, 256, MLP0_SMEM>>>(node_feat, w0a, b0a, w0b, b0b);  // overlapped

    // join both directions: layers need CSR (sB) + e0 (s0) on BOTH streams
    cudaEventRecord(evB, sB);
    cudaStreamWaitEvent(0, evB, 0);
    cudaEventRecord(evA, 0);
    cudaStreamWaitEvent(sB, evA, 0);

    // 3 GNN layers, producer/consumer pipelined:
    //   stream 0: spmm chunks (LSU/L2-bound) back-to-back
    //   stream B: mlp chunks (FMA-bound), each gated on its spmm chunk
    for (int l = 0; l < L_LAYERS; l++) {
        for (int c = 0; c < N_CHUNKS; c++) {
            k_spmm<<<CHUNK / 16, 256, 0, 0>>>(e[l], c * CHUNK);
            cudaEventRecord(evS[c], 0);
        }
        for (int c = 0; c < N_CHUNKS; c++) {
            cudaStreamWaitEvent(sB, evS[c], 0);
            k_mlp1<<<MLP1_GRID, 256, 0, sB>>>(W1a, B1a, W1b, B1b, e[l], e[l + 1],
                                              l, c * CHUNK, (c + 1) * CHUNK);
        }
        // layer join: next layer's spmm (s0) gathers ALL rows of e[l+1] (sB)
        cudaEventRecord(evB, sB);
        cudaStreamWaitEvent(0, evB, 0);
    }

    // sort pooling + alpha combine (stream B has the final mlp chunks)
    k_topk<<<B_G, 256, 0, sB>>>(alpha, dout);

    // ensure the capture's terminal node is on the default stream
    cudaEventRecord(evB, sB);
    cudaStreamWaitEvent(0, evB, 0);
}

// round 17
// speedup vs baseline: 1.3129x; 1.3129x over previous
#include <cuda_runtime.h>
#include <math.h>

#define N_NODES 128000
#define N_HALF  64000
#define F_IN    128
#define D_LAT   32
#define B_G     256
#define NPG     500
#define K_TOP   30
#define L_LAYERS 3
#define E_EDGES 2048000

// packed f32x2 add (Blackwell): only reachable via PTX. Used ONLY where both
// operands are naturally 64-bit register pairs (LDG.64 results).
__device__ __forceinline__ void add2(float2& a, float2 b) {
    unsigned long long au = *reinterpret_cast<unsigned long long*>(&a);
    unsigned long long bu = *reinterpret_cast<unsigned long long*>(&b);
    asm("add.rn.f32x2 %0, %1, %2;" : "=l"(au) : "l"(au), "l"(bu));
    a = *reinterpret_cast<float2*>(&au);
}

// ---------------- device scratch (static, no allocation) ----------------
__device__ float g_e0[N_NODES * D_LAT];
__device__ float g_e1[N_NODES * D_LAT];
__device__ float g_e2[N_NODES * D_LAT];
__device__ float g_e3[N_NODES * D_LAT];
__device__ float g_neig[N_NODES * D_LAT];
__device__ int   g_counts[N_NODES];
__device__ int   g_rowptr[N_NODES + 1];
__device__ int   g_cursor[N_NODES];
__device__ int   g_bsums[128];
__device__ int   g_col[E_EDGES];

// ---------------- edge histogram (stream B) ----------------
__global__ void k_hist(const int4* __restrict__ edst4) {
    if (blockIdx.x == 0 && threadIdx.x < 128) g_bsums[threadIdx.x] = 0;  // scan flags
    int i = blockIdx.x * blockDim.x + threadIdx.x;
    int4 v = edst4[i];
    atomicAdd(&g_counts[v.x], 1);
    atomicAdd(&g_counts[v.y], 1);
    atomicAdd(&g_counts[v.z], 1);
    atomicAdd(&g_counts[v.w], 1);
}

// ---------------- mlp0: ego0 = relu(X@w0a+b0a)@w0b+b0b ---------------------
// Warp per 16 rows: 1 weight-LDS feeds 16 FMAs; 16-deep row ILP hides LDS lat.
#define MLP0_GRID 1000
#define MLP0_SMEM (F_IN * D_LAT * 4 + 8 * 16 * F_IN * 4)   // 16KB + 64KB
__global__ void __launch_bounds__(256, 2) k_mlp0(
        const float* __restrict__ X,
        const float* __restrict__ w0a, const float* __restrict__ b0a,
        const float* __restrict__ w0b, const float* __restrict__ b0b) {
    extern __shared__ float smem0[];
    float* ws = smem0;                          // w0a [k][lane], 16KB
    float* sx = smem0 + F_IN * D_LAT;           // 16 rows x 128 floats per warp
    int tid  = threadIdx.x;
    int lane = tid & 31;
    int w    = tid >> 5;

    for (int i = tid; i < F_IN * D_LAT; i += 256) ws[i] = w0a[i];
    float wb[32];
    #pragma unroll
    for (int j = 0; j < 32; j++) wb[j] = w0b[j * 32 + lane];
    float b0 = b0a[lane], b1 = b0b[lane];
    __syncthreads();

    int warp  = blockIdx.x * 8 + w;
    int rbase = warp * 16;
    float* xw = &sx[w * 2048];

    #pragma unroll
    for (int rr = 0; rr < 16; rr++) {
        float4 v = *(const float4*)&X[(rbase + rr) * F_IN + lane * 4];
        *(float4*)&xw[rr * 128 + lane * 4] = v;
    }
    __syncwarp();

    float acc[16];
    #pragma unroll
    for (int rr = 0; rr < 16; rr++) acc[rr] = b0;
    #pragma unroll 2
    for (int k = 0; k < F_IN; k += 4) {
        float w0 = ws[(k + 0) * 32 + lane];
        float w1 = ws[(k + 1) * 32 + lane];
        float w2 = ws[(k + 2) * 32 + lane];
        float w3 = ws[(k + 3) * 32 + lane];
        #pragma unroll
        for (int rr = 0; rr < 16; rr++) {
            float4 x4 = *(const float4*)&xw[rr * 128 + k];
            float p0 = fmaf(x4.x, w0, acc[rr]);
            float p1 = fmaf(x4.y, w1, p0);
            float p2 = fmaf(x4.z, w2, p1);
            acc[rr]  = fmaf(x4.w, w3, p2);
        }
    }
    float h[16];
    #pragma unroll
    for (int rr = 0; rr < 16; rr++) h[rr] = fmaxf(acc[rr], 0.f);

    __syncwarp();
    #pragma unroll
    for (int rr = 0; rr < 16; rr++) xw[rr * 32 + lane] = h[rr];
    __syncwarp();

    float o[16];
    #pragma unroll
    for (int rr = 0; rr < 16; rr++) o[rr] = b1;
    #pragma unroll
    for (int j = 0; j < 32; j += 4) {
        #pragma unroll
        for (int rr = 0; rr < 16; rr++) {
            float4 h4 = *(const float4*)&xw[rr * 32 + j];
            float p0 = fmaf(h4.x, wb[j + 0], o[rr]);
            float p1 = fmaf(h4.y, wb[j + 1], p0);
            float p2 = fmaf(h4.z, wb[j + 2], p1);
            o[rr]    = fmaf(h4.w, wb[j + 3], p2);
        }
    }
    #pragma unroll
    for (int rr = 0; rr < 16; rr++)
        g_e0[(rbase + rr) * 32 + lane] = o[rr];
}

// ------------- single-pass scan: counts -> rowptr/cursor (lookback) --------
#define SCAN_FLAG 0x40000000
__global__ void __launch_bounds__(1024) k_scan() {
    __shared__ int swarp[32];
    __shared__ int sbase;
    int tid  = threadIdx.x;
    int lane = tid & 31;
    int wid  = tid >> 5;
    int b    = blockIdx.x;
    int gid  = b * 1024 + tid;

    int v = g_counts[gid];
    int x = v;
    #pragma unroll
    for (int off = 1; off < 32; off <<= 1) {
        int t = __shfl_up_sync(0xFFFFFFFFu, x, off);
        if (lane >= off) x += t;
    }
    if (lane == 31) swarp[wid] = x;
    __syncthreads();
    if (wid == 0) {
        int y = swarp[lane];
        #pragma unroll
        for (int off = 1; off < 32; off <<= 1) {
            int t = __shfl_up_sync(0xFFFFFFFFu, y, off);
            if (lane >= off) y += t;
        }
        swarp[lane] = y;
    }
    __syncthreads();
    int wbase = (wid > 0) ? swarp[wid - 1] : 0;
    int local_excl = wbase + x - v;
    int blocksum   = swarp[31];

    if (tid == 0) {
        __threadfence();
        atomicExch(&g_bsums[b], blocksum | SCAN_FLAG);
    }
    if (wid == 0) {
        int pre = 0;
        for (int i = lane; i < b; i += 32) {
            int t;
            do { t = atomicAdd(&g_bsums[i], 0); } while (!(t & SCAN_FLAG));
            pre += t & (SCAN_FLAG - 1);
        }
        #pragma unroll
        for (int off = 16; off >= 1; off >>= 1)
            pre += __shfl_down_sync(0xFFFFFFFFu, pre, off);
        if (lane == 0) sbase = pre;
    }
    __syncthreads();
    int rp = sbase + local_excl;
    g_rowptr[gid] = rp;
    g_cursor[gid] = rp;
    if (gid == N_NODES - 1) g_rowptr[N_NODES] = E_EDGES;
}

__global__ void k_scatter(const int4* __restrict__ esrc4, const int4* __restrict__ edst4) {
    int i = blockIdx.x * blockDim.x + threadIdx.x;
    int4 s = esrc4[i];
    int4 d = edst4[i];
    int p;
    p = atomicAdd(&g_cursor[d.x], 1); g_col[p] = s.x;
    p = atomicAdd(&g_cursor[d.y], 1); g_col[p] = s.y;
    p = atomicAdd(&g_cursor[d.z], 1); g_col[p] = s.z;
    p = atomicAdd(&g_cursor[d.w], 1); g_col[p] = s.w;
}

// ---------------- SpMM over node range [lo, lo+64000) ----------------------
// Each 16-lane half-warp owns ONE node. Lane = float2 (2 channels). (R12 form)
__global__ void __launch_bounds__(256) k_spmm(const float* __restrict__ ego_in,
                                              int lo) {
    int gwarp = (blockIdx.x * blockDim.x + threadIdx.x) >> 5;
    int lane  = threadIdx.x & 31;
    int half  = lane >> 4;
    int li    = lane & 15;
    int node  = lo + gwarp * 2 + half;
    int e   = g_rowptr[node];
    int end = g_rowptr[node + 1];
    const float2* __restrict__ eg2 = (const float2*)ego_in;

    float2 a0 = make_float2(0.f, 0.f);
    float2 a1 = make_float2(0.f, 0.f);
    float2 a2 = make_float2(0.f, 0.f);
    float2 a3 = make_float2(0.f, 0.f);

    for (; e + 3 < end; e += 4) {
        int s0 = g_col[e + 0];
        int s1 = g_col[e + 1];
        int s2 = g_col[e + 2];
        int s3 = g_col[e + 3];
        float2 v0 = eg2[s0 * 16 + li];
        float2 v1 = eg2[s1 * 16 + li];
        float2 v2 = eg2[s2 * 16 + li];
        float2 v3 = eg2[s3 * 16 + li];
        add2(a0, v0);
        add2(a1, v1);
        add2(a2, v2);
        add2(a3, v3);
    }
    for (; e < end; e++) {
        int s = g_col[e];
        add2(a0, eg2[s * 16 + li]);
    }
    add2(a0, a1);
    add2(a2, a3);
    add2(a0, a2);

    ((float2*)g_neig)[node * 16 + li] = a0;
}

// ---------------- layer MLP over row range [lo, hi) -------------------------
#define MLP1_GRID 296
__global__ void __launch_bounds__(256, 2) k_mlp1(
        const float* __restrict__ W1a, const float* __restrict__ B1a,
        const float* __restrict__ W1b, const float* __restrict__ B1b,
        const float* __restrict__ ego_in, float* __restrict__ ego_out,
        int l, int lo, int hi) {
    __shared__ float sm[8 * 96];
    int tid  = threadIdx.x;
    int lane = tid & 31;
    float* sw = &sm[(tid >> 5) * 96];

    const float* Wa = W1a + l * 96 * 32;
    const float* Wb = W1b + l * 32 * 32;
    float wea[32], wna[32], wb[32];
    #pragma unroll
    for (int j = 0; j < 32; j++) {
        float wc = Wa[(64 + j) * 32 + lane];
        wea[j] = Wa[j * 32 + lane] + wc;
        wna[j] = Wa[(32 + j) * 32 + lane] + wc;
        wb[j]  = Wb[j * 32 + lane];
    }
    float ba = B1a[l * 32 + lane], bb = B1b[l * 32 + lane];

    int warp   = (blockIdx.x * 256 + tid) >> 5;
    int nwarps = (MLP1_GRID * 256) >> 5;

    int row = lo + warp;
    float ev = 0.f, nv = 0.f;
    if (row < hi) {
        ev = ego_in[row * 32 + lane];
        nv = g_neig[row * 32 + lane];
    }
    for (; row < hi; row += nwarps) {
        int nrow = row + nwarps;
        float evn = 0.f, nvn = 0.f;
        if (nrow < hi) {
            evn = ego_in[nrow * 32 + lane];
            nvn = g_neig[nrow * 32 + lane];
        }

        sw[lane]      = ev;
        sw[32 + lane] = nv;
        __syncwarp();

        float e0 = ba, e1 = 0.f, e2 = 0.f, e3 = 0.f;
        float n0 = 0.f, n1 = 0.f, n2 = 0.f, n3 = 0.f;
        #pragma unroll
        for (int j = 0; j < 32; j += 4) {
            float4 e4 = *(const float4*)&sw[j];
            float4 n4 = *(const float4*)&sw[32 + j];
            e0 = fmaf(e4.x, wea[j + 0], e0);
            e1 = fmaf(e4.y, wea[j + 1], e1);
            e2 = fmaf(e4.z, wea[j + 2], e2);
            e3 = fmaf(e4.w, wea[j + 3], e3);
            n0 = fmaf(n4.x, wna[j + 0], n0);
            n1 = fmaf(n4.y, wna[j + 1], n1);
            n2 = fmaf(n4.z, wna[j + 2], n2);
            n3 = fmaf(n4.w, wna[j + 3], n3);
        }
        float h = fmaxf(((e0 + e1) + (e2 + e3)) + ((n0 + n1) + (n2 + n3)), 0.f);
        sw[64 + lane] = h;
        __syncwarp();

        float o0 = bb, o1 = 0.f, o2 = 0.f, o3 = 0.f;
        #pragma unroll
        for (int j = 0; j < 32; j += 4) {
            float4 h4 = *(const float4*)&sw[64 + j];
            o0 = fmaf(h4.x, wb[j + 0], o0);
            o1 = fmaf(h4.y, wb[j + 1], o1);
            o2 = fmaf(h4.z, wb[j + 2], o2);
            o3 = fmaf(h4.w, wb[j + 3], o3);
        }
        ego_out[row * 32 + lane] = (o0 + o1) + (o2 + o3);
        __syncwarp();
        ev = evn; nv = nvn;
    }
}

// ---------------- per-graph top-K + alpha combine + relu -------------------
// Register-resident candidates (2/thread) + warp-shuffle argmax per round.
// Order: value desc, ties -> lower index (matches jax.lax.top_k).
__global__ void k_topk(const float* __restrict__ alpha, float* __restrict__ dout) {
    __shared__ float wv[8];
    __shared__ int   wi[8];
    __shared__ int   sel[K_TOP];
    __shared__ int   bestIdx;
    int g = blockIdx.x, tid = threadIdx.x;     // 256 threads
    int lane = tid & 31, wid = tid >> 5;

    // two candidates per thread in registers
    int   i0 = tid, i1 = tid + 256;
    float v0 = (i0 < NPG) ? g_e3[(g * NPG + i0) * 32 + 31] : -3.402823466e38f;
    float v1 = (i1 < NPG) ? g_e3[(g * NPG + i1) * 32 + 31] : -3.402823466e38f;

    for (int r = 0; r < K_TOP; r++) {
        // local best of the two register slots
        float bv; int bi;
        if (v0 > v1 || (v0 == v1 && i0 < i1)) { bv = v0; bi = i0; }
        else                                  { bv = v1; bi = i1; }
        // warp argmax (desc value, lower index on tie)
        #pragma unroll
        for (int off = 16; off >= 1; off >>= 1) {
            float ov = __shfl_down_sync(0xFFFFFFFFu, bv, off);
            int   oi = __shfl_down_sync(0xFFFFFFFFu, bi, off);
            if (ov > bv || (ov == bv && oi < bi)) { bv = ov; bi = oi; }
        }
        if (lane == 0) { wv[wid] = bv; wi[wid] = bi; }
        __syncthreads();
        if (tid == 0) {
            float fv = wv[0]; int fi = wi[0];
            #pragma unroll
            for (int k = 1; k < 8; k++) {
                if (wv[k] > fv || (wv[k] == fv && wi[k] < fi)) { fv = wv[k]; fi = wi[k]; }
            }
            sel[r] = fi;
            bestIdx = fi;
        }
        __syncthreads();
        // remove the selected candidate
        int win = bestIdx;
        if (i0 == win) v0 = -3.402823466e38f;
        if (i1 == win) v1 = -3.402823466e38f;
    }

    float a0v = alpha[0], a1v = alpha[1], a2v = alpha[2], a3v = alpha[3];
    for (int i = tid; i < K_TOP * 32; i += 256) {
        int r = i >> 5, c = i & 31;
        int idx = (g * NPG + sel[r]) * 32 + c;
        float v = a0v * g_e0[idx];
        v = fmaf(a1v, g_e1[idx], v);
        v = fmaf(a2v, g_e2[idx], v);
        v = fmaf(a3v, g_e3[idx], v);
        dout[g * (K_TOP * 32) + i] = fmaxf(v, 0.f);
    }
}

// ---------------- launch -----------------------------------------------
extern "C" void kernel_launch(void* const* d_in, const int* in_sizes, int n_in,
                              void* d_out, int out_size) {
    const float* node_feat = (const float*)d_in[0];
    const float* alpha     = (const float*)d_in[1];
    const float* w0a       = (const float*)d_in[2];
    const float* b0a       = (const float*)d_in[3];
    const float* w0b       = (const float*)d_in[4];
    const float* b0b       = (const float*)d_in[5];
    const float* W1a       = (const float*)d_in[6];
    const float* B1a       = (const float*)d_in[7];
    const float* W1b       = (const float*)d_in[8];
    const float* B1b       = (const float*)d_in[9];
    const int*   esrc      = (const int*)d_in[10];
    const int*   edst      = (const int*)d_in[11];
    float*       dout      = (float*)d_out;

    static cudaStream_t sB = nullptr;
    static cudaEvent_t  evFork = nullptr, evA = nullptr, evB = nullptr;
    if (sB == nullptr) {
        cudaStreamCreateWithFlags(&sB, cudaStreamNonBlocking);
        cudaEventCreateWithFlags(&evFork, cudaEventDisableTiming);
        cudaEventCreateWithFlags(&evA, cudaEventDisableTiming);
        cudaEventCreateWithFlags(&evB, cudaEventDisableTiming);
        cudaFuncSetAttribute(k_mlp0, cudaFuncAttributeMaxDynamicSharedMemorySize,
                             MLP0_SMEM);
    }

    void* counts_ptr = nullptr;
    cudaGetSymbolAddress(&counts_ptr, g_counts);

    float* e[4];
    {
        void* p;
        cudaGetSymbolAddress(&p, g_e0); e[0] = (float*)p;
        cudaGetSymbolAddress(&p, g_e1); e[1] = (float*)p;
        cudaGetSymbolAddress(&p, g_e2); e[2] = (float*)p;
        cudaGetSymbolAddress(&p, g_e3); e[3] = (float*)p;
    }

    // fork: stream B builds the CSR while stream 0 runs mlp0
    cudaEventRecord(evFork, 0);
    cudaStreamWaitEvent(sB, evFork, 0);

    cudaMemsetAsync(counts_ptr, 0, N_NODES * sizeof(int), sB);
    k_hist<<<E_EDGES / 4 / 256, 256, 0, sB>>>((const int4*)edst);
    k_scan<<<125, 1024, 0, sB>>>();
    k_scatter<<<E_EDGES / 4 / 256, 256, 0, sB>>>((const int4*)esrc, (const int4*)edst);

    k_mlp0<<<MLP0_GRID, 256, MLP0_SMEM>>>(node_feat, w0a, b0a, w0b, b0b);  // overlapped

    // join both directions: layers need CSR (sB) + e0 (s0) on BOTH streams
    cudaEventRecord(evB, sB);
    cudaStreamWaitEvent(0, evB, 0);
    cudaEventRecord(evA, 0);
    cudaStreamWaitEvent(sB, evA, 0);

    // 3 GNN layers: two independent half-chains per layer on two streams.
    // chain0 (s0): spmm rows [0,64k) -> mlp rows [0,64k)
    // chain1 (sB): spmm rows [64k,128k) -> mlp rows [64k,128k)
    for (int l = 0; l < L_LAYERS; l++) {
        k_spmm<<<4000, 256, 0, 0>>>(e[l], 0);
        k_mlp1<<<MLP1_GRID, 256, 0, 0>>>(W1a, B1a, W1b, B1b, e[l], e[l + 1],
                                         l, 0, N_HALF);
        k_spmm<<<4000, 256, 0, sB>>>(e[l], N_HALF);
        k_mlp1<<<MLP1_GRID, 256, 0, sB>>>(W1a, B1a, W1b, B1b, e[l], e[l + 1],
                                          l, N_HALF, N_NODES);
        // cross-join: next layer's gathers read ALL rows of e[l+1]
        cudaEventRecord(evB, sB);
        cudaStreamWaitEvent(0, evB, 0);
        cudaEventRecord(evA, 0);
        cudaStreamWaitEvent(sB, evA, 0);
    }

    // sort pooling + alpha combine
    k_topk<<<B_G, 256>>>(alpha, dout);
}